// round 14
// baseline (speedup 1.0000x reference)
#include <cuda_runtime.h>
#include <cuda_bf16.h>
#include <cstdint>

// ---------------- problem constants ----------------
#define BATCH 64
#define NV 512
#define NT 512
#define DIM 768
#define EPS_F 0.1f
#define TAU_F 0.005f
#define DELTA_F 1e-9f
#define E1 2.718281828459045f   // exp(gamma/eps)
#define MU1 (1.0f + 1e-9f)
#define ITERS 5
#define TILES 8                 // CTAs per batch (cluster size)

// ---------------- device scratch (never pass as host-side kernel args) ----------
__device__ __nv_bfloat16 g_vn[(size_t)BATCH * NV * DIM];
__device__ __nv_bfloat16 g_tn[(size_t)BATCH * NT * DIM];
__device__ __nv_bfloat16 g_Kexp[(size_t)BATCH * NV * NT];
__device__ int   g_lenv[BATCH];
__device__ int   g_lent[BATCH];
__device__ float g_a[BATCH * 512];
__device__ float g_b[BATCH * 512];
__device__ float g_wv[BATCH * NV];
__device__ float g_wtp[(size_t)BATCH * TILES * 512];
__device__ float g_lossp[BATCH * TILES];
__device__ float g_loss[BATCH];

#define CLUSTER_SYNC_()                                                  \
    do {                                                                 \
        asm volatile("barrier.cluster.arrive.aligned;" ::: "memory");    \
        asm volatile("barrier.cluster.wait.aligned;" ::: "memory");      \
    } while (0)

// ---------------- lengths ----------------
__global__ void len_kernel(const void* m, int which) {
    int b = blockIdx.x;
    const unsigned char* mb = (const unsigned char*)m;
    bool is8 = (mb[1] != 0);  // len >= 256 so element 1 is true
    int t = threadIdx.x;
    int val;
    if (is8) val = (mb[(size_t)b * 512 + t] != 0) ? 1 : 0;
    else     val = (((const int*)m)[(size_t)b * 512 + t] != 0) ? 1 : 0;
#pragma unroll
    for (int o = 16; o; o >>= 1) val += __shfl_xor_sync(0xffffffffu, val, o);
    __shared__ int sw[16];
    if ((t & 31) == 0) sw[t >> 5] = val;
    __syncthreads();
    if (t < 32) {
        int x = (t < 16) ? sw[t] : 0;
#pragma unroll
        for (int o = 8; o; o >>= 1) x += __shfl_xor_sync(0xffffffffu, x, o);
        if (t == 0) { if (which) g_lent[b] = x; else g_lenv[b] = x; }
    }
}

// ---------------- normalize + convert to bf16 ----------------
__global__ __launch_bounds__(256) void prep_kernel(const float* __restrict__ v,
                                                   const float* __restrict__ t) {
    int warp = threadIdx.x >> 5, lane = threadIdx.x & 31;
    int row = blockIdx.x * 8 + warp;
    const float* src = blockIdx.y ? t : v;
    __nv_bfloat16* dst = blockIdx.y ? g_tn : g_vn;
    const float4* p = (const float4*)(src + (size_t)row * DIM);
    float4 q[6];
    float s = 0.f;
#pragma unroll
    for (int j = 0; j < 6; j++) {
        q[j] = p[lane + 32 * j];
        s += q[j].x * q[j].x + q[j].y * q[j].y + q[j].z * q[j].z + q[j].w * q[j].w;
    }
#pragma unroll
    for (int o = 16; o; o >>= 1) s += __shfl_xor_sync(0xffffffffu, s, o);
    float r = rsqrtf(fmaxf(s, 1e-24f));
    __nv_bfloat162* d = (__nv_bfloat162*)(dst + (size_t)row * DIM);
#pragma unroll
    for (int j = 0; j < 6; j++) {
        int c2 = 2 * (lane + 32 * j);
        d[c2]     = __float22bfloat162_rn(make_float2(q[j].x * r, q[j].y * r));
        d[c2 + 1] = __float22bfloat162_rn(make_float2(q[j].z * r, q[j].w * r));
    }
}

// ---------------- GEMM: bf16 mma m16n8k16, 3-stage cp.async + masked-tile skip ---
#define BM 128
#define BN 128
#define BK 32
#define ST 40
#define KSTEPS (DIM / BK)
#define OPBYTES (BM * ST * 2)
#define STAGE_BYTES (2 * OPBYTES)
#define GEMM_SMEM (3 * STAGE_BYTES)

#define CP16(dst, src) asm volatile("cp.async.cg.shared.global [%0], [%1], 16;\n" :: "r"(dst), "l"(src))
#define CPCOMMIT() asm volatile("cp.async.commit_group;\n" ::: "memory")

__device__ __forceinline__ void mma_bf16(float* c, uint32_t a0, uint32_t a1, uint32_t a2,
                                         uint32_t a3, uint32_t b0, uint32_t b1) {
    asm volatile(
        "mma.sync.aligned.m16n8k16.row.col.f32.bf16.bf16.f32 "
        "{%0,%1,%2,%3},{%4,%5,%6,%7},{%8,%9},{%0,%1,%2,%3};\n"
        : "+f"(c[0]), "+f"(c[1]), "+f"(c[2]), "+f"(c[3])
        : "r"(a0), "r"(a1), "r"(a2), "r"(a3), "r"(b0), "r"(b1));
}

__device__ __forceinline__ void ldsm4(uint32_t& r0, uint32_t& r1, uint32_t& r2,
                                      uint32_t& r3, uint32_t addr) {
    asm volatile("ldmatrix.sync.aligned.m8n8.x4.shared.b16 {%0,%1,%2,%3}, [%4];\n"
                 : "=r"(r0), "=r"(r1), "=r"(r2), "=r"(r3) : "r"(addr));
}

__global__ __launch_bounds__(256, 2) void gemm_kernel() {
    extern __shared__ __align__(16) __nv_bfloat16 dsm[];
    int bn = blockIdx.x, bm = blockIdx.y, bz = blockIdx.z;
    int tid = threadIdx.x;

    int lv = g_lenv[bz], lt = g_lent[bz];

    // masked-tile early exit: whole 128x128 tile is exp(NEG)=0 -> zero-fill, done.
    if (bm * BM >= lv || bn * BN >= lt) {
        __nv_bfloat16* dst = g_Kexp + ((size_t)bz * NV + bm * BM) * NT + bn * BN;
#pragma unroll
        for (int i = 0; i < 8; i++) {
            int u = tid + 256 * i;
            int row = u >> 4, c16 = (u & 15) * 8;
            *(uint4*)(dst + (size_t)row * NT + c16) = make_uint4(0, 0, 0, 0);
        }
        return;
    }

    int warp = tid >> 5, lane = tid & 31;
    int wm = warp >> 2, wn = warp & 3;
    int g = lane >> 2, tg = lane & 3;

    const __nv_bfloat16* Ap = g_vn + ((size_t)bz * NV + bm * BM) * DIM;
    const __nv_bfloat16* Bp = g_tn + ((size_t)bz * NT + bn * BN) * DIM;
    uint32_t smBase = (uint32_t)__cvta_generic_to_shared(dsm);

    float acc[4][4][4];
#pragma unroll
    for (int i = 0; i < 4; i++)
#pragma unroll
        for (int j = 0; j < 4; j++)
#pragma unroll
            for (int k = 0; k < 4; k++) acc[i][j][k] = 0.f;

#define LOAD_STAGE(S, K0)                                                       \
    {                                                                           \
        uint32_t oA = smBase + (S) * STAGE_BYTES;                               \
        uint32_t oB = oA + OPBYTES;                                             \
        _Pragma("unroll")                                                       \
        for (int i = 0; i < 2; i++) {                                           \
            int u = tid + 256 * i;                                              \
            int row = u >> 2, c = (u & 3) * 8;                                  \
            CP16(oA + (uint32_t)(row * ST + c) * 2, Ap + (size_t)row * DIM + (K0) + c); \
            CP16(oB + (uint32_t)(row * ST + c) * 2, Bp + (size_t)row * DIM + (K0) + c); \
        }                                                                       \
    }

    LOAD_STAGE(0, 0);
    CPCOMMIT();
    LOAD_STAGE(1, BK);
    CPCOMMIT();

    int aRow = (lane & 7) + ((lane >> 3) & 1) * 8;
    int aCol = (lane >> 4) * 8;
    int bRow = (lane & 7) + (lane >> 4) * 8;
    int bCol = ((lane >> 3) & 1) * 8;

#pragma unroll 3
    for (int ks = 0; ks < KSTEPS; ks++) {
        if (ks + 1 < KSTEPS)
            asm volatile("cp.async.wait_group 1;\n" ::: "memory");
        else
            asm volatile("cp.async.wait_group 0;\n" ::: "memory");
        __syncthreads();
        if (ks + 2 < KSTEPS) {
            LOAD_STAGE((ks + 2) % 3, (ks + 2) * BK);
            CPCOMMIT();
        }
        uint32_t As = smBase + (ks % 3) * STAGE_BYTES;
        uint32_t Bs = As + OPBYTES;
#pragma unroll
        for (int kk = 0; kk < 2; kk++) {
            int koff = kk * 16;
            uint32_t af[4][4], bf[2][4];
#pragma unroll
            for (int mt = 0; mt < 4; mt++) {
                int row = wm * 64 + mt * 16 + aRow;
                ldsm4(af[mt][0], af[mt][1], af[mt][2], af[mt][3],
                      As + (uint32_t)(row * ST + koff + aCol) * 2);
            }
#pragma unroll
            for (int nb = 0; nb < 2; nb++) {
                int row = wn * 32 + nb * 16 + bRow;
                ldsm4(bf[nb][0], bf[nb][1], bf[nb][2], bf[nb][3],
                      Bs + (uint32_t)(row * ST + koff + bCol) * 2);
            }
#pragma unroll
            for (int mt = 0; mt < 4; mt++)
#pragma unroll
                for (int nt = 0; nt < 4; nt++) {
                    int nb = nt >> 1, hi = (nt & 1) * 2;
                    mma_bf16(acc[mt][nt], af[mt][0], af[mt][1], af[mt][2], af[mt][3],
                             bf[nb][hi], bf[nb][hi + 1]);
                }
        }
    }

#pragma unroll
    for (int mt = 0; mt < 4; mt++) {
        int m0 = bm * BM + wm * 64 + mt * 16 + g;
        bool v0ok = (m0 < lv), v1ok = (m0 + 8 < lv);
#pragma unroll
        for (int nt = 0; nt < 4; nt++) {
            int n0 = bn * BN + wn * 32 + nt * 8 + 2 * tg;
            bool t0ok = (n0 < lt), t1ok = (n0 + 1 < lt);
            float* a = acc[mt][nt];
            float e00 = (v0ok && t0ok) ? __expf(a[0] * 10.f) : 0.f;
            float e01 = (v0ok && t1ok) ? __expf(a[1] * 10.f) : 0.f;
            float e10 = (v1ok && t0ok) ? __expf(a[2] * 10.f) : 0.f;
            float e11 = (v1ok && t1ok) ? __expf(a[3] * 10.f) : 0.f;
            size_t base = ((size_t)bz * NV + m0) * NT + n0;
            *(__nv_bfloat162*)(g_Kexp + base) = __float22bfloat162_rn(make_float2(e00, e01));
            *(__nv_bfloat162*)(g_Kexp + base + 8 * NT) = __float22bfloat162_rn(make_float2(e10, e11));
        }
    }
}

// ---------------- block reduce over 512 threads ----------------
__device__ __forceinline__ float blockReduceSum512(float x, float* sred) {
    int lane = threadIdx.x & 31, w = threadIdx.x >> 5;
#pragma unroll
    for (int o = 16; o; o >>= 1) x += __shfl_xor_sync(0xffffffffu, x, o);
    __syncthreads();
    if (lane == 0) sred[w] = x;
    __syncthreads();
    if (w == 0) {
        float y = (lane < 16) ? sred[lane] : 0.f;
#pragma unroll
        for (int o = 8; o; o >>= 1) y += __shfl_xor_sync(0xffffffffu, y, o);
        if (lane == 0) sred[16] = y;
    }
    __syncthreads();
    return sred[16];
}

// ---------------- fused Sinkhorn + finalize (R9 structure, TILES=8) ---------------
// 512 CTAs (8 per batch); each CTA: 64 rows (row phase), 64-col slice (col phase).
__global__ __cluster_dims__(8, 1, 1) __launch_bounds__(512)
void sinkhorn_fused(float* __restrict__ out) {
    int cid = blockIdx.x;
    int b = cid >> 3, tile = cid & 7;
    int tid = threadIdx.x, lane = tid & 31, warp = tid >> 5;
    __shared__ __align__(16) float sv[513];
    __shared__ float scol[16][512];            // finalize col partials (32KB)
    __shared__ float sred[32];
    float* sc2 = &scol[0][0];                  // col phase: [32][65] view (2080 < 8192)

    const __nv_bfloat16* KE = g_Kexp + (size_t)b * NV * NT;
    int lv = g_lenv[b], lt = g_lent[b];
    float muP = 1.0f / ((float)lv + 1e-9f) + 1e-9f;
    float nuP = 1.0f / ((float)lt + 1e-9f) + 1e-9f;
    float b512 = 1.0f, a512 = 0.f, suma_real = 0.f;

    for (int it = 0; it < ITERS; it++) {
        // ---- row phase: a_r = mu'_r / (K b + e1*b512); 4 rows per warp
        sv[tid] = (it == 0) ? 1.0f : __ldcg(&g_b[b * 512 + tid]);
        __syncthreads();
        float sumb = blockReduceSum512(sv[tid], sred) + b512;
        a512 = MU1 / (E1 * sumb);
        float den1 = E1 * b512;
#pragma unroll
        for (int j = 0; j < 4; j++) {
            int r = tile * 64 + warp * 4 + j;
            const uint4* kp = (const uint4*)(KE + (size_t)r * NT);
            float s = 0.f;
#pragma unroll
            for (int jj = 0; jj < 2; jj++) {
                int idx = lane + 32 * jj;
                uint4 q = kp[idx];
                const float* b8 = sv + 8 * idx;
                float2 f0 = __bfloat1622float2(*(const __nv_bfloat162*)&q.x);
                float2 f1 = __bfloat1622float2(*(const __nv_bfloat162*)&q.y);
                float2 f2 = __bfloat1622float2(*(const __nv_bfloat162*)&q.z);
                float2 f3 = __bfloat1622float2(*(const __nv_bfloat162*)&q.w);
                s += f0.x * b8[0] + f0.y * b8[1] + f1.x * b8[2] + f1.y * b8[3];
                s += f2.x * b8[4] + f2.y * b8[5] + f3.x * b8[6] + f3.y * b8[7];
            }
#pragma unroll
            for (int o = 16; o; o >>= 1) s += __shfl_xor_sync(0xffffffffu, s, o);
            if (lane == 0)
                __stcg(&g_a[b * 512 + r], ((r < lv) ? muP : 1e-9f) / (s + den1));
        }
        __threadfence();
        CLUSTER_SYNC_();

        // ---- col phase: b_c = nu'_c / (K^T a + e1*a512); 64-col slice
        sv[tid] = __ldcg(&g_a[b * 512 + tid]);
        __syncthreads();
        suma_real = blockReduceSum512(sv[tid], sred);
        b512 = MU1 / (E1 * (suma_real + a512));
        {
            int colOff = (lane & 15) * 4;                  // 0..60
            int rBase = warp * 32 + (lane >> 4) * 16;      // 16 rows per half-warp
            const __nv_bfloat16* KEc = KE + tile * 64 + colOff;
            float s0 = 0.f, s1 = 0.f, s2 = 0.f, s3 = 0.f;
            for (int r = rBase; r < rBase + 16; r++) {
                uint2 q = *(const uint2*)(KEc + (size_t)r * NT);
                float2 f0 = __bfloat1622float2(*(const __nv_bfloat162*)&q.x);
                float2 f1 = __bfloat1622float2(*(const __nv_bfloat162*)&q.y);
                float ar = sv[r];
                s0 += f0.x * ar; s1 += f0.y * ar; s2 += f1.x * ar; s3 += f1.y * ar;
            }
            int p = warp * 2 + (lane >> 4);                // 0..31
            sc2[p * 65 + colOff + 0] = s0;
            sc2[p * 65 + colOff + 1] = s1;
            sc2[p * 65 + colOff + 2] = s2;
            sc2[p * 65 + colOff + 3] = s3;
        }
        __syncthreads();
        if (tid < 64) {
            float tot = 0.f;
#pragma unroll
            for (int p = 0; p < 32; p++) tot += sc2[p * 65 + tid];
            int c = tile * 64 + tid;
            __stcg(&g_b[b * 512 + c], ((c < lt) ? nuP : 1e-9f) / (tot + E1 * a512));
        }
        __threadfence();
        CLUSTER_SYNC_();
    }

    // ---- finalize: wv rowsums, wt col partials, loss partials
    sv[tid] = __ldcg(&g_b[b * 512 + tid]);
    __syncthreads();
    float sumb_real = blockReduceSum512(sv[tid], sred);

    float colacc[16];
#pragma unroll
    for (int i = 0; i < 16; i++) colacc[i] = 0.f;
    float lp = 0.f;
#pragma unroll
    for (int j = 0; j < 4; j++) {
        int r = tile * 64 + warp * 4 + j;
        float ar = __ldcg(&g_a[b * 512 + r]);
        const uint4* kp = (const uint4*)(KE + (size_t)r * NT);
        float rowsum = 0.f;
#pragma unroll
        for (int jj = 0; jj < 2; jj++) {
            int idx = lane + 32 * jj;
            uint4 q = kp[idx];
            const float* b8 = sv + 8 * idx;
            float ke[8];
            float2 f;
            f = __bfloat1622float2(*(const __nv_bfloat162*)&q.x); ke[0] = f.x; ke[1] = f.y;
            f = __bfloat1622float2(*(const __nv_bfloat162*)&q.y); ke[2] = f.x; ke[3] = f.y;
            f = __bfloat1622float2(*(const __nv_bfloat162*)&q.z); ke[4] = f.x; ke[5] = f.y;
            f = __bfloat1622float2(*(const __nv_bfloat162*)&q.w); ke[6] = f.x; ke[7] = f.y;
#pragma unroll
            for (int e = 0; e < 8; e++) {
                float T = ar * ke[e] * b8[e];
                float th = fmaxf(T - TAU_F, 0.f);
                rowsum += th;
                colacc[jj * 8 + e] += th;
                if (ke[e] > 0.f) lp += T * (1.0f - EPS_F * __logf(ke[e]));
            }
        }
#pragma unroll
        for (int o = 16; o; o >>= 1) rowsum += __shfl_xor_sync(0xffffffffu, rowsum, o);
        if (lane == 0) __stcg(&g_wv[b * 512 + r], rowsum);
    }
    __syncthreads();   // sc2 reads (col phase of last iter) complete before overwrite
#pragma unroll
    for (int jj = 0; jj < 2; jj++)
#pragma unroll
        for (int e = 0; e < 8; e++)
            scol[warp][8 * (lane + 32 * jj) + e] = colacc[jj * 8 + e];
    __syncthreads();
    {
        float cs = 0.f;
#pragma unroll
        for (int w = 0; w < 16; w++) cs += scol[w][tid];
        __stcg(&g_wtp[((size_t)b * TILES + tile) * 512 + tid], cs);
    }
    float ltot = blockReduceSum512(lp, sred);
    if (tid == 0) __stcg(&g_lossp[b * TILES + tile], ltot);
    __threadfence();
    CLUSTER_SYNC_();

    // ---- tail: tile 0 normalizes weights + assembles loss
    if (tile == 0) {
        float wt = DELTA_F;
#pragma unroll
        for (int i = 0; i < TILES; i++)
            wt += __ldcg(&g_wtp[((size_t)b * TILES + i) * 512 + tid]);
        float tott = blockReduceSum512(wt, sred);
        out[1 + BATCH * NV + b * 512 + tid] = wt / tott;

        float wv = __ldcg(&g_wv[b * 512 + tid]) + DELTA_F;
        float totv = blockReduceSum512(wv, sred);
        out[1 + b * 512 + tid] = wv / totv;

        float lpart = (tid < TILES) ? __ldcg(&g_lossp[b * TILES + tid]) : 0.f;
        float lt2 = blockReduceSum512(lpart, sred);
        if (tid == 0)
            g_loss[b] = lt2 + E1 * 0.9f * (a512 * (sumb_real + b512) + b512 * suma_real);
    }
}

// ---------------- mean loss ----------------
__global__ void loss_mean_kernel(float* __restrict__ out) {
    int t = threadIdx.x;  // 64
    float x = g_loss[t];
#pragma unroll
    for (int o = 16; o; o >>= 1) x += __shfl_xor_sync(0xffffffffu, x, o);
    __shared__ float s2[2];
    if ((t & 31) == 0) s2[t >> 5] = x;
    __syncthreads();
    if (t == 0) out[0] = (s2[0] + s2[1]) * (1.0f / 64.0f);
}

// ---------------- launch ----------------
extern "C" void kernel_launch(void* const* d_in, const int* in_sizes, int n_in,
                              void* d_out, int out_size) {
    const float* v = (const float*)d_in[0];
    const float* t = (const float*)d_in[1];
    const void* vm = d_in[2];
    const void* tm = d_in[3];
    float* out = (float*)d_out;

    cudaFuncSetAttribute(gemm_kernel, cudaFuncAttributeMaxDynamicSharedMemorySize, GEMM_SMEM);

    len_kernel<<<64, 512>>>(vm, 0);                      // launch 1
    len_kernel<<<64, 512>>>(tm, 1);                      // launch 2
    prep_kernel<<<dim3(4096, 2), 256>>>(v, t);           // launch 3
    gemm_kernel<<<dim3(4, 4, 64), 256, GEMM_SMEM>>>();   // launch 4 (profiled slot)
    sinkhorn_fused<<<512, 512>>>(out);                   // launch 5
    loss_mean_kernel<<<1, 64>>>(out);                    // launch 6
}

// round 15
// speedup vs baseline: 1.1182x; 1.1182x over previous
#include <cuda_runtime.h>
#include <cuda_bf16.h>
#include <cstdint>

// ---------------- problem constants ----------------
#define BATCH 64
#define NV 512
#define NT 512
#define DIM 768
#define EPS_F 0.1f
#define TAU_F 0.005f
#define DELTA_F 1e-9f
#define E1 2.718281828459045f   // exp(gamma/eps)
#define MU1 (1.0f + 1e-9f)
#define ITERS 5
#define TILES 4                 // CTAs per batch (cluster size; 4 is proven optimal)

// ---------------- device scratch (never pass as host-side kernel args) ----------
__device__ __nv_bfloat16 g_vn[(size_t)BATCH * NV * DIM];
__device__ __nv_bfloat16 g_tn[(size_t)BATCH * NT * DIM];
__device__ __nv_bfloat16 g_Kexp[(size_t)BATCH * NV * NT];
__device__ int   g_lenv[BATCH];
__device__ int   g_lent[BATCH];
__device__ float g_a[BATCH * 512];
__device__ float g_b[BATCH * 512];
__device__ float g_wv[BATCH * NV];
__device__ float g_wtp[(size_t)BATCH * TILES * 512];
__device__ float g_lossp[BATCH * TILES];
__device__ float g_loss[BATCH];

#define CLUSTER_SYNC_()                                                  \
    do {                                                                 \
        asm volatile("barrier.cluster.arrive.aligned;" ::: "memory");    \
        asm volatile("barrier.cluster.wait.aligned;" ::: "memory");      \
    } while (0)

// ---------------- lengths ----------------
__global__ void len_kernel(const void* m, int which) {
    int b = blockIdx.x;
    const unsigned char* mb = (const unsigned char*)m;
    bool is8 = (mb[1] != 0);  // len >= 256 so element 1 is true
    int t = threadIdx.x;
    int val;
    if (is8) val = (mb[(size_t)b * 512 + t] != 0) ? 1 : 0;
    else     val = (((const int*)m)[(size_t)b * 512 + t] != 0) ? 1 : 0;
#pragma unroll
    for (int o = 16; o; o >>= 1) val += __shfl_xor_sync(0xffffffffu, val, o);
    __shared__ int sw[16];
    if ((t & 31) == 0) sw[t >> 5] = val;
    __syncthreads();
    if (t < 32) {
        int x = (t < 16) ? sw[t] : 0;
#pragma unroll
        for (int o = 8; o; o >>= 1) x += __shfl_xor_sync(0xffffffffu, x, o);
        if (t == 0) { if (which) g_lent[b] = x; else g_lenv[b] = x; }
    }
}

// ---------------- normalize + convert to bf16 ----------------
__global__ __launch_bounds__(256) void prep_kernel(const float* __restrict__ v,
                                                   const float* __restrict__ t) {
    int warp = threadIdx.x >> 5, lane = threadIdx.x & 31;
    int row = blockIdx.x * 8 + warp;
    const float* src = blockIdx.y ? t : v;
    __nv_bfloat16* dst = blockIdx.y ? g_tn : g_vn;
    const float4* p = (const float4*)(src + (size_t)row * DIM);
    float4 q[6];
    float s = 0.f;
#pragma unroll
    for (int j = 0; j < 6; j++) {
        q[j] = p[lane + 32 * j];
        s += q[j].x * q[j].x + q[j].y * q[j].y + q[j].z * q[j].z + q[j].w * q[j].w;
    }
#pragma unroll
    for (int o = 16; o; o >>= 1) s += __shfl_xor_sync(0xffffffffu, s, o);
    float r = rsqrtf(fmaxf(s, 1e-24f));
    __nv_bfloat162* d = (__nv_bfloat162*)(dst + (size_t)row * DIM);
#pragma unroll
    for (int j = 0; j < 6; j++) {
        int c2 = 2 * (lane + 32 * j);
        d[c2]     = __float22bfloat162_rn(make_float2(q[j].x * r, q[j].y * r));
        d[c2 + 1] = __float22bfloat162_rn(make_float2(q[j].z * r, q[j].w * r));
    }
}

// ---------------- GEMM: bf16 mma m16n8k16, BM=64, BN=128, 3 CTAs/SM -------------
#define BM 64
#define BN 128
#define BK 32
#define ST 40
#define KSTEPS (DIM / BK)            // 24
#define OPBYTES_A (BM * ST * 2)      // 5120
#define OPBYTES_B (BN * ST * 2)      // 10240
#define STAGE_BYTES (OPBYTES_A + OPBYTES_B)  // 15360
#define GEMM_SMEM (3 * STAGE_BYTES)  // 46080

#define CP16(dst, src) asm volatile("cp.async.cg.shared.global [%0], [%1], 16;\n" :: "r"(dst), "l"(src))
#define CPCOMMIT() asm volatile("cp.async.commit_group;\n" ::: "memory")

__device__ __forceinline__ void mma_bf16(float* c, uint32_t a0, uint32_t a1, uint32_t a2,
                                         uint32_t a3, uint32_t b0, uint32_t b1) {
    asm volatile(
        "mma.sync.aligned.m16n8k16.row.col.f32.bf16.bf16.f32 "
        "{%0,%1,%2,%3},{%4,%5,%6,%7},{%8,%9},{%0,%1,%2,%3};\n"
        : "+f"(c[0]), "+f"(c[1]), "+f"(c[2]), "+f"(c[3])
        : "r"(a0), "r"(a1), "r"(a2), "r"(a3), "r"(b0), "r"(b1));
}

__device__ __forceinline__ void ldsm4(uint32_t& r0, uint32_t& r1, uint32_t& r2,
                                      uint32_t& r3, uint32_t addr) {
    asm volatile("ldmatrix.sync.aligned.m8n8.x4.shared.b16 {%0,%1,%2,%3}, [%4];\n"
                 : "=r"(r0), "=r"(r1), "=r"(r2), "=r"(r3) : "r"(addr));
}

__global__ __launch_bounds__(256, 3) void gemm_kernel() {
    extern __shared__ __align__(16) __nv_bfloat16 dsm[];
    int bn = blockIdx.x, bm = blockIdx.y, bz = blockIdx.z;
    int tid = threadIdx.x;

    int lv = g_lenv[bz], lt = g_lent[bz];

    // masked-tile early exit: whole 64x128 tile is exp(NEG)=0 -> zero-fill, done.
    if (bm * BM >= lv || bn * BN >= lt) {
        __nv_bfloat16* dst = g_Kexp + ((size_t)bz * NV + bm * BM) * NT + bn * BN;
#pragma unroll
        for (int i = 0; i < 4; i++) {
            int u = tid + 256 * i;            // 0..1023
            int row = u >> 4, c16 = (u & 15) * 8;
            *(uint4*)(dst + (size_t)row * NT + c16) = make_uint4(0, 0, 0, 0);
        }
        return;
    }

    int warp = tid >> 5, lane = tid & 31;
    int wm = warp >> 2, wn = warp & 3;       // warp tile: 32(M) x 32(N)
    int g = lane >> 2, tg = lane & 3;

    const __nv_bfloat16* Ap = g_vn + ((size_t)bz * NV + bm * BM) * DIM;
    const __nv_bfloat16* Bp = g_tn + ((size_t)bz * NT + bn * BN) * DIM;
    uint32_t smBase = (uint32_t)__cvta_generic_to_shared(dsm);

    float acc[2][4][4];
#pragma unroll
    for (int i = 0; i < 2; i++)
#pragma unroll
        for (int j = 0; j < 4; j++)
#pragma unroll
            for (int k = 0; k < 4; k++) acc[i][j][k] = 0.f;

    // stage: A 64 rows x 4 chunks(16B) = 256 chunks; B 128 rows x 4 = 512 chunks
#define LOAD_STAGE(S, K0)                                                       \
    {                                                                           \
        uint32_t oA = smBase + (S) * STAGE_BYTES;                               \
        uint32_t oB = oA + OPBYTES_A;                                           \
        {                                                                       \
            int u = tid;                                                        \
            int row = u >> 2, c = (u & 3) * 8;                                  \
            CP16(oA + (uint32_t)(row * ST + c) * 2, Ap + (size_t)row * DIM + (K0) + c); \
        }                                                                       \
        _Pragma("unroll")                                                       \
        for (int i = 0; i < 2; i++) {                                           \
            int u = tid + 256 * i;                                              \
            int row = u >> 2, c = (u & 3) * 8;                                  \
            CP16(oB + (uint32_t)(row * ST + c) * 2, Bp + (size_t)row * DIM + (K0) + c); \
        }                                                                       \
    }

    LOAD_STAGE(0, 0);
    CPCOMMIT();
    LOAD_STAGE(1, BK);
    CPCOMMIT();

    int aRow = (lane & 7) + ((lane >> 3) & 1) * 8;
    int aCol = (lane >> 4) * 8;
    int bRow = (lane & 7) + (lane >> 4) * 8;
    int bCol = ((lane >> 3) & 1) * 8;

#pragma unroll 3
    for (int ks = 0; ks < KSTEPS; ks++) {
        if (ks + 1 < KSTEPS)
            asm volatile("cp.async.wait_group 1;\n" ::: "memory");
        else
            asm volatile("cp.async.wait_group 0;\n" ::: "memory");
        __syncthreads();
        if (ks + 2 < KSTEPS) {
            LOAD_STAGE((ks + 2) % 3, (ks + 2) * BK);
            CPCOMMIT();
        }
        uint32_t As = smBase + (ks % 3) * STAGE_BYTES;
        uint32_t Bs = As + OPBYTES_A;
#pragma unroll
        for (int kk = 0; kk < 2; kk++) {
            int koff = kk * 16;
            uint32_t af[2][4], bf[2][4];
#pragma unroll
            for (int mt = 0; mt < 2; mt++) {
                int row = wm * 32 + mt * 16 + aRow;
                ldsm4(af[mt][0], af[mt][1], af[mt][2], af[mt][3],
                      As + (uint32_t)(row * ST + koff + aCol) * 2);
            }
#pragma unroll
            for (int nb = 0; nb < 2; nb++) {
                int row = wn * 32 + nb * 16 + bRow;
                ldsm4(bf[nb][0], bf[nb][1], bf[nb][2], bf[nb][3],
                      Bs + (uint32_t)(row * ST + koff + bCol) * 2);
            }
#pragma unroll
            for (int mt = 0; mt < 2; mt++)
#pragma unroll
                for (int nt = 0; nt < 4; nt++) {
                    int nb = nt >> 1, hi = (nt & 1) * 2;
                    mma_bf16(acc[mt][nt], af[mt][0], af[mt][1], af[mt][2], af[mt][3],
                             bf[nb][hi], bf[nb][hi + 1]);
                }
        }
    }

#pragma unroll
    for (int mt = 0; mt < 2; mt++) {
        int m0 = bm * BM + wm * 32 + mt * 16 + g;
        bool v0ok = (m0 < lv), v1ok = (m0 + 8 < lv);
#pragma unroll
        for (int nt = 0; nt < 4; nt++) {
            int n0 = bn * BN + wn * 32 + nt * 8 + 2 * tg;
            bool t0ok = (n0 < lt), t1ok = (n0 + 1 < lt);
            float* a = acc[mt][nt];
            float e00 = (v0ok && t0ok) ? __expf(a[0] * 10.f) : 0.f;
            float e01 = (v0ok && t1ok) ? __expf(a[1] * 10.f) : 0.f;
            float e10 = (v1ok && t0ok) ? __expf(a[2] * 10.f) : 0.f;
            float e11 = (v1ok && t1ok) ? __expf(a[3] * 10.f) : 0.f;
            size_t base = ((size_t)bz * NV + m0) * NT + n0;
            *(__nv_bfloat162*)(g_Kexp + base) = __float22bfloat162_rn(make_float2(e00, e01));
            *(__nv_bfloat162*)(g_Kexp + base + 8 * NT) = __float22bfloat162_rn(make_float2(e10, e11));
        }
    }
}

// ---------------- block reduce over 512 threads ----------------
__device__ __forceinline__ float blockReduceSum512(float x, float* sred) {
    int lane = threadIdx.x & 31, w = threadIdx.x >> 5;
#pragma unroll
    for (int o = 16; o; o >>= 1) x += __shfl_xor_sync(0xffffffffu, x, o);
    __syncthreads();
    if (lane == 0) sred[w] = x;
    __syncthreads();
    if (w == 0) {
        float y = (lane < 16) ? sred[lane] : 0.f;
#pragma unroll
        for (int o = 8; o; o >>= 1) y += __shfl_xor_sync(0xffffffffu, y, o);
        if (lane == 0) sred[16] = y;
    }
    __syncthreads();
    return sred[16];
}

// ---------------- fused Sinkhorn + finalize (R13-verbatim, TILES=4) ---------------
__global__ __cluster_dims__(4, 1, 1) __launch_bounds__(512)
void sinkhorn_fused(float* __restrict__ out) {
    int cid = blockIdx.x;
    int b = cid >> 2, tile = cid & 3;
    int tid = threadIdx.x, lane = tid & 31, warp = tid >> 5;
    __shared__ __align__(16) float sv[513];
    __shared__ float scol[16][512];
    __shared__ float sred[32];

    const __nv_bfloat16* KE = g_Kexp + (size_t)b * NV * NT;
    int lv = g_lenv[b], lt = g_lent[b];
    float muP = 1.0f / ((float)lv + 1e-9f) + 1e-9f;
    float nuP = 1.0f / ((float)lt + 1e-9f) + 1e-9f;
    float b512 = 1.0f, a512 = 0.f, suma_real = 0.f;

    for (int it = 0; it < ITERS; it++) {
        // ---- row phase: a_r = mu'_r / (K b + e1*b512)
        sv[tid] = (it == 0) ? 1.0f : __ldcg(&g_b[b * 512 + tid]);
        __syncthreads();
        float sumb = blockReduceSum512(sv[tid], sred) + b512;
        a512 = MU1 / (E1 * sumb);
        float den1 = E1 * b512;
#pragma unroll
        for (int j = 0; j < 8; j++) {
            int r = tile * 128 + warp * 8 + j;
            const uint4* kp = (const uint4*)(KE + (size_t)r * NT);
            float s = 0.f;
#pragma unroll
            for (int jj = 0; jj < 2; jj++) {
                int idx = lane + 32 * jj;
                uint4 q = kp[idx];
                const float* b8 = sv + 8 * idx;
                float2 f0 = __bfloat1622float2(*(const __nv_bfloat162*)&q.x);
                float2 f1 = __bfloat1622float2(*(const __nv_bfloat162*)&q.y);
                float2 f2 = __bfloat1622float2(*(const __nv_bfloat162*)&q.z);
                float2 f3 = __bfloat1622float2(*(const __nv_bfloat162*)&q.w);
                s += f0.x * b8[0] + f0.y * b8[1] + f1.x * b8[2] + f1.y * b8[3];
                s += f2.x * b8[4] + f2.y * b8[5] + f3.x * b8[6] + f3.y * b8[7];
            }
#pragma unroll
            for (int o = 16; o; o >>= 1) s += __shfl_xor_sync(0xffffffffu, s, o);
            if (lane == 0)
                __stcg(&g_a[b * 512 + r], ((r < lv) ? muP : 1e-9f) / (s + den1));
        }
        __threadfence();
        CLUSTER_SYNC_();

        // ---- col phase: b_c = nu'_c / (K^T a + e1*a512)
        sv[tid] = __ldcg(&g_a[b * 512 + tid]);
        __syncthreads();
        suma_real = blockReduceSum512(sv[tid], sred);
        b512 = MU1 / (E1 * (suma_real + a512));
        {
            const __nv_bfloat16* KEc = KE + tile * 128 + lane * 4;
            float s0 = 0.f, s1 = 0.f, s2 = 0.f, s3 = 0.f;
            for (int r = warp * 32; r < warp * 32 + 32; r++) {
                uint2 q = *(const uint2*)(KEc + (size_t)r * NT);
                float2 f0 = __bfloat1622float2(*(const __nv_bfloat162*)&q.x);
                float2 f1 = __bfloat1622float2(*(const __nv_bfloat162*)&q.y);
                float ar = sv[r];
                s0 += f0.x * ar; s1 += f0.y * ar; s2 += f1.x * ar; s3 += f1.y * ar;
            }
            scol[warp][lane * 4 + 0] = s0;
            scol[warp][lane * 4 + 1] = s1;
            scol[warp][lane * 4 + 2] = s2;
            scol[warp][lane * 4 + 3] = s3;
        }
        __syncthreads();
        if (tid < 128) {
            float tot = 0.f;
#pragma unroll
            for (int w = 0; w < 16; w++) tot += scol[w][tid];
            int c = tile * 128 + tid;
            __stcg(&g_b[b * 512 + c], ((c < lt) ? nuP : 1e-9f) / (tot + E1 * a512));
        }
        __threadfence();
        CLUSTER_SYNC_();
    }

    // ---- finalize: wv rowsums, wt col partials, loss partials
    sv[tid] = __ldcg(&g_b[b * 512 + tid]);
    __syncthreads();
    float sumb_real = blockReduceSum512(sv[tid], sred);

    float colacc[16];
#pragma unroll
    for (int i = 0; i < 16; i++) colacc[i] = 0.f;
    float lp = 0.f;
#pragma unroll
    for (int j = 0; j < 8; j++) {
        int r = tile * 128 + warp * 8 + j;
        float ar = __ldcg(&g_a[b * 512 + r]);
        const uint4* kp = (const uint4*)(KE + (size_t)r * NT);
        float rowsum = 0.f;
#pragma unroll
        for (int jj = 0; jj < 2; jj++) {
            int idx = lane + 32 * jj;
            uint4 q = kp[idx];
            const float* b8 = sv + 8 * idx;
            float ke[8];
            float2 f;
            f = __bfloat1622float2(*(const __nv_bfloat162*)&q.x); ke[0] = f.x; ke[1] = f.y;
            f = __bfloat1622float2(*(const __nv_bfloat162*)&q.y); ke[2] = f.x; ke[3] = f.y;
            f = __bfloat1622float2(*(const __nv_bfloat162*)&q.z); ke[4] = f.x; ke[5] = f.y;
            f = __bfloat1622float2(*(const __nv_bfloat162*)&q.w); ke[6] = f.x; ke[7] = f.y;
#pragma unroll
            for (int e = 0; e < 8; e++) {
                float T = ar * ke[e] * b8[e];
                float th = fmaxf(T - TAU_F, 0.f);
                rowsum += th;
                colacc[jj * 8 + e] += th;
                if (ke[e] > 0.f) lp += T * (1.0f - EPS_F * __logf(ke[e]));
            }
        }
#pragma unroll
        for (int o = 16; o; o >>= 1) rowsum += __shfl_xor_sync(0xffffffffu, rowsum, o);
        if (lane == 0) __stcg(&g_wv[b * 512 + r], rowsum);
    }
#pragma unroll
    for (int jj = 0; jj < 2; jj++)
#pragma unroll
        for (int e = 0; e < 8; e++)
            scol[warp][8 * (lane + 32 * jj) + e] = colacc[jj * 8 + e];
    __syncthreads();
    {
        float cs = 0.f;
#pragma unroll
        for (int w = 0; w < 16; w++) cs += scol[w][tid];
        __stcg(&g_wtp[((size_t)b * 4 + tile) * 512 + tid], cs);
    }
    float ltot = blockReduceSum512(lp, sred);
    if (tid == 0) __stcg(&g_lossp[b * 4 + tile], ltot);
    __threadfence();
    CLUSTER_SYNC_();

    // ---- tail: tile 0 normalizes weights + assembles loss
    if (tile == 0) {
        float wt = DELTA_F;
#pragma unroll
        for (int i = 0; i < 4; i++) wt += __ldcg(&g_wtp[((size_t)b * 4 + i) * 512 + tid]);
        float tott = blockReduceSum512(wt, sred);
        out[1 + BATCH * NV + b * 512 + tid] = wt / tott;

        float wv = __ldcg(&g_wv[b * 512 + tid]) + DELTA_F;
        float totv = blockReduceSum512(wv, sred);
        out[1 + b * 512 + tid] = wv / totv;

        float lpart = (tid < 4) ? __ldcg(&g_lossp[b * 4 + tid]) : 0.f;
        float lt2 = blockReduceSum512(lpart, sred);
        if (tid == 0)
            g_loss[b] = lt2 + E1 * 0.9f * (a512 * (sumb_real + b512) + b512 * suma_real);
    }
}

// ---------------- mean loss ----------------
__global__ void loss_mean_kernel(float* __restrict__ out) {
    int t = threadIdx.x;  // 64
    float x = g_loss[t];
#pragma unroll
    for (int o = 16; o; o >>= 1) x += __shfl_xor_sync(0xffffffffu, x, o);
    __shared__ float s2[2];
    if ((t & 31) == 0) s2[t >> 5] = x;
    __syncthreads();
    if (t == 0) out[0] = (s2[0] + s2[1]) * (1.0f / 64.0f);
}

// ---------------- launch ----------------
extern "C" void kernel_launch(void* const* d_in, const int* in_sizes, int n_in,
                              void* d_out, int out_size) {
    const float* v = (const float*)d_in[0];
    const float* t = (const float*)d_in[1];
    const void* vm = d_in[2];
    const void* tm = d_in[3];
    float* out = (float*)d_out;

    cudaFuncSetAttribute(gemm_kernel, cudaFuncAttributeMaxDynamicSharedMemorySize, GEMM_SMEM);

    len_kernel<<<64, 512>>>(vm, 0);                      // launch 1
    len_kernel<<<64, 512>>>(tm, 1);                      // launch 2
    prep_kernel<<<dim3(4096, 2), 256>>>(v, t);           // launch 3
    gemm_kernel<<<dim3(4, 8, 64), 256, GEMM_SMEM>>>();   // launch 4 (profiled slot)
    sinkhorn_fused<<<256, 512>>>(out);                   // launch 5
    loss_mean_kernel<<<1, 64>>>(out);                    // launch 6
}